// round 6
// baseline (speedup 1.0000x reference)
#include <cuda_runtime.h>
#include <cuda_fp16.h>

#define N_INST 200000
#define N_NETN 50000
#define NN     250000
#define NE     2000000
#define NSCANB 245   // ceil(250000/1024)

// ---------------- device scratch (no runtime allocation allowed) ----------------
__device__ float g_xf[(size_t)NN * 64];       // x_f = h @ Wf + bf (fp32, self term)
__device__ float g_xr[(size_t)NN * 64];       // x_r = h @ Wr + br
__device__ uint2 g_yf[(size_t)NN * 16];       // relu(x_f) fp16, 4 features per uint2
__device__ uint2 g_yr[(size_t)NN * 16];       // relu(x_r) fp16
__device__ float g_tmp[(size_t)N_INST * 128]; // encoder hidden (inst)
__device__ float g_tmpn[(size_t)N_NETN * 64]; // encoder hidden (net)
__device__ float g_disf[NN], g_disr[NN];      // deg^-1/2
__device__ float g_idegf[NN], g_idegr[NN];    // deg^-1
__device__ int   g_cntf[NN], g_cntr[NN];      // edge counts (row / col)
__device__ int   g_offF[NN], g_offR[NN];      // CSR bucket starts
__device__ int   g_fillF[NN], g_fillR[NN];
__device__ int   g_bsF[256], g_bsR[256];      // scan block sums
__device__ int2  g_csrF[NE + 64];             // (src, norm) keyed by col, padded
__device__ int2  g_csrR[NE + 64];             // (src, norm) keyed by row, padded

// ---------------- helpers ----------------
__device__ __forceinline__ float leaky(float v) { return fmaxf(v, 0.1f * v); }

__device__ __forceinline__ unsigned long long dup64(float a) {
    unsigned long long r;
    asm("mov.b64 %0, {%1, %1};" : "=l"(r) : "f"(a));
    return r;
}
__device__ __forceinline__ float2 up64(unsigned long long v) {
    float2 r;
    asm("mov.b64 {%0, %1}, %2;" : "=f"(r.x), "=f"(r.y) : "l"(v));
    return r;
}
__device__ __forceinline__ void fma2(unsigned long long& d,
                                     unsigned long long a,
                                     unsigned long long b) {
    asm("fma.rn.f32x2 %0, %1, %2, %0;" : "+l"(d) : "l"(a), "l"(b));
}
__device__ __forceinline__ void acc4(float4& a, uint2 g, float s) {
    float2 lo = __half22float2(*(const __half2*)&g.x);
    float2 hi = __half22float2(*(const __half2*)&g.y);
    a.x += lo.x * s; a.y += lo.y * s; a.z += hi.x * s; a.w += hi.y * s;
}

// ---------------- degree counting ----------------
__global__ __launch_bounds__(256) void k_count(const int* __restrict__ ei) {
    int e = blockIdx.x * 256 + threadIdx.x;
    if (e >= NE) return;
    atomicAdd(&g_cntf[ei[e]], 1);
    atomicAdd(&g_cntr[ei[NE + e]], 1);
}

__global__ __launch_bounds__(256) void k_deg() {
    int n = blockIdx.x * 256 + threadIdx.x;
    if (n >= NN) return;
    float df = (float)g_cntf[n] + 1.0f;
    float dr = (float)g_cntr[n] + 1.0f;
    g_disf[n] = rsqrtf(df);
    g_disr[n] = rsqrtf(dr);
    g_idegf[n] = 1.0f / df;
    g_idegr[n] = 1.0f / dr;
}

// ---------------- exclusive scan ----------------
__global__ __launch_bounds__(256) void k_scan1(const int* __restrict__ cnt,
                                               int* __restrict__ off,
                                               int* __restrict__ bsum) {
    __shared__ int wsum[8];
    int tid = threadIdx.x, lane = tid & 31, w = tid >> 5;
    int base = blockIdx.x * 1024 + tid * 4;
    int v0 = (base + 0 < NN) ? cnt[base + 0] : 0;
    int v1 = (base + 1 < NN) ? cnt[base + 1] : 0;
    int v2 = (base + 2 < NN) ? cnt[base + 2] : 0;
    int v3 = (base + 3 < NN) ? cnt[base + 3] : 0;
    int s = v0 + v1 + v2 + v3;
    int x = s;
#pragma unroll
    for (int o = 1; o < 32; o <<= 1) {
        int y = __shfl_up_sync(0xffffffffu, x, o);
        if (lane >= o) x += y;
    }
    if (lane == 31) wsum[w] = x;
    __syncthreads();
    if (tid == 0) {
        int r = 0;
#pragma unroll
        for (int j = 0; j < 8; j++) { int t = wsum[j]; wsum[j] = r; r += t; }
        bsum[blockIdx.x] = r;
    }
    __syncthreads();
    int ex = wsum[w] + x - s;
    if (base + 0 < NN) off[base + 0] = ex;
    if (base + 1 < NN) off[base + 1] = ex + v0;
    if (base + 2 < NN) off[base + 2] = ex + v0 + v1;
    if (base + 3 < NN) off[base + 3] = ex + v0 + v1 + v2;
}

__global__ __launch_bounds__(256) void k_scan2(int* __restrict__ bsum, int nb) {
    __shared__ int sm[256];
    int tid = threadIdx.x;
    int v = (tid < nb) ? bsum[tid] : 0;
    sm[tid] = v;
    __syncthreads();
#pragma unroll
    for (int o = 1; o < 256; o <<= 1) {
        int t = (tid >= o) ? sm[tid - o] : 0;
        __syncthreads();
        sm[tid] += t;
        __syncthreads();
    }
    if (tid < nb) bsum[tid] = sm[tid] - v;
}

__global__ __launch_bounds__(256) void k_scan3(int* __restrict__ off,
                                               const int* __restrict__ bsum) {
    int add = bsum[blockIdx.x];
    int base = blockIdx.x * 1024 + threadIdx.x * 4;
#pragma unroll
    for (int i = 0; i < 4; i++)
        if (base + i < NN) off[base + i] += add;
}

// ---------------- CSR placement with per-edge norms ----------------
__global__ __launch_bounds__(256) void k_place(const int* __restrict__ ei) {
    int e = blockIdx.x * 256 + threadIdx.x;
    if (e >= NE) return;
    int a = __ldg(ei + e);
    int b = __ldg(ei + NE + e);
    float nf = __ldg(&g_disf[a]) * __ldg(&g_disf[b]);
    float nr = __ldg(&g_disr[b]) * __ldg(&g_disr[a]);
    int pf = g_offF[b] + atomicAdd(&g_fillF[b], 1);
    g_csrF[pf] = make_int2(a, __float_as_int(nf));
    int pr = g_offR[a] + atomicAdd(&g_fillR[a], 1);
    g_csrR[pr] = make_int2(b, __float_as_int(nr));
    if (e < 64) {   // init safety padding (points at node 0, norm 0)
        g_csrF[NE + e] = make_int2(0, 0);
        g_csrR[NE + e] = make_int2(0, 0);
    }
}

// ---------------- encoder stage 1 ----------------
template<int KIN, int KOUT, int NPB>
__global__ __launch_bounds__(256) void k_encA(
    const float* __restrict__ x, const float* __restrict__ W,
    const float* __restrict__ bias, float* __restrict__ tmp, int nNodes)
{
    __shared__ float xs[NPB * KIN];
    int tid = threadIdx.x;
    int base = blockIdx.x * NPB;
    const int NSUB = 256 / KOUT;
#pragma unroll
    for (int i = 0; i < (NPB * KIN + 255) / 256; i++) {
        int idx = tid + i * 256;
        if (idx < NPB * KIN) {
            size_t gidx = (size_t)base * KIN + idx;
            size_t mx = (size_t)nNodes * KIN - 1;
            xs[idx] = x[gidx <= mx ? gidx : mx];
        }
    }
    int j = tid & (KOUT - 1);
    int nsub = tid / KOUT;
    float wcol[KIN];
#pragma unroll
    for (int k = 0; k < KIN; k++) wcol[k] = W[k * KOUT + j];
    float bj = bias[j];
    __syncthreads();
#pragma unroll
    for (int t = 0; t < NPB / NSUB; t++) {
        int n = nsub + t * NSUB;
        float a = bj;
#pragma unroll
        for (int k4 = 0; k4 < KIN; k4 += 4) {
            float4 xv = *(const float4*)&xs[n * KIN + k4];
            a += xv.x * wcol[k4] + xv.y * wcol[k4 + 1]
               + xv.z * wcol[k4 + 2] + xv.w * wcol[k4 + 3];
        }
        if (base + n < nNodes)
            tmp[(size_t)(base + n) * KOUT + j] = leaky(a);
    }
}

// ---------------- register-tiled GEMM: dst = act(src @ W + b) ----------------
template<int KTOT, bool LEAKY, bool WRELU>
__global__ __launch_bounds__(128) void k_mm(
    const float* __restrict__ src, int srcStride, int srcOff, int srcBase,
    const float* __restrict__ W, const float* __restrict__ bias,
    float* __restrict__ dst, int dstStride, int dstOff, int dstBase,
    uint2* __restrict__ yout, int nNodes)
{
    __shared__ float hs[64 * 68];
    __shared__ float ws[64 * 64];
    int tid = threadIdx.x;
    int tb = blockIdx.x * 64;
    int tx = tid & 15, ty = tid >> 4;
    int bn = ty * 8;
    unsigned long long acc[4][4];
#pragma unroll
    for (int a = 0; a < 4; a++)
#pragma unroll
        for (int b = 0; b < 4; b++) acc[a][b] = 0ull;

    int c = tid & 63, r = tid >> 6;
    for (int kc = 0; kc < KTOT; kc += 64) {
        if (kc) __syncthreads();
#pragma unroll
        for (int i = 0; i < 32; i++)
            ws[tid + i * 128] = W[kc * 64 + tid + i * 128];
#pragma unroll
        for (int i = 0; i < 32; i++) {
            int nl = i * 2 + r;
            int g = tb + nl; if (g >= nNodes) g = nNodes - 1;
            hs[c * 68 + nl] = src[(size_t)(srcBase + g) * srcStride + srcOff + kc + c];
        }
        __syncthreads();
#pragma unroll 4
        for (int k = 0; k < 64; k++) {
            float4 wf = *(const float4*)&ws[k * 64 + tx * 4];
            unsigned long long dw0 = dup64(wf.x);
            unsigned long long dw1 = dup64(wf.y);
            unsigned long long dw2 = dup64(wf.z);
            unsigned long long dw3 = dup64(wf.w);
            ulonglong2 hA = *(const ulonglong2*)&hs[k * 68 + bn];
            ulonglong2 hB = *(const ulonglong2*)&hs[k * 68 + bn + 4];
            fma2(acc[0][0], hA.x, dw0); fma2(acc[0][1], hA.x, dw1);
            fma2(acc[0][2], hA.x, dw2); fma2(acc[0][3], hA.x, dw3);
            fma2(acc[1][0], hA.y, dw0); fma2(acc[1][1], hA.y, dw1);
            fma2(acc[1][2], hA.y, dw2); fma2(acc[1][3], hA.y, dw3);
            fma2(acc[2][0], hB.x, dw0); fma2(acc[2][1], hB.x, dw1);
            fma2(acc[2][2], hB.x, dw2); fma2(acc[2][3], hB.x, dw3);
            fma2(acc[3][0], hB.y, dw0); fma2(acc[3][1], hB.y, dw1);
            fma2(acc[3][2], hB.y, dw2); fma2(acc[3][3], hB.y, dw3);
        }
    }
    float4 bv = *(const float4*)&bias[tx * 4];
#pragma unroll
    for (int np = 0; np < 4; np++) {
        int n0 = tb + bn + np * 2;
        float2 v0 = up64(acc[np][0]);
        float2 v1 = up64(acc[np][1]);
        float2 v2 = up64(acc[np][2]);
        float2 v3 = up64(acc[np][3]);
        float4 o0 = make_float4(v0.x + bv.x, v1.x + bv.y, v2.x + bv.z, v3.x + bv.w);
        float4 o1 = make_float4(v0.y + bv.x, v1.y + bv.y, v2.y + bv.z, v3.y + bv.w);
        if (LEAKY) {
            o0 = make_float4(leaky(o0.x), leaky(o0.y), leaky(o0.z), leaky(o0.w));
            o1 = make_float4(leaky(o1.x), leaky(o1.y), leaky(o1.z), leaky(o1.w));
        }
        if (n0 < nNodes) {
            __stcs((float4*)&dst[(size_t)(dstBase + n0) * dstStride + dstOff + tx * 4], o0);
            if (WRELU) {
                __half2 h0 = __float22half2_rn(make_float2(fmaxf(o0.x, 0.f), fmaxf(o0.y, 0.f)));
                __half2 h1 = __float22half2_rn(make_float2(fmaxf(o0.z, 0.f), fmaxf(o0.w, 0.f)));
                yout[(size_t)n0 * 16 + tx] = make_uint2(*(unsigned*)&h0, *(unsigned*)&h1);
            }
        }
        if (n0 + 1 < nNodes) {
            __stcs((float4*)&dst[(size_t)(dstBase + n0 + 1) * dstStride + dstOff + tx * 4], o1);
            if (WRELU) {
                __half2 h0 = __float22half2_rn(make_float2(fmaxf(o1.x, 0.f), fmaxf(o1.y, 0.f)));
                __half2 h1 = __float22half2_rn(make_float2(fmaxf(o1.z, 0.f), fmaxf(o1.w, 0.f)));
                yout[(size_t)(n0 + 1) * 16 + tx] = make_uint2(*(unsigned*)&h0, *(unsigned*)&h1);
            }
        }
    }
}

// ---------------- fused dual-chain pipelined aggregation + LN + leaky ----------------
// Warp per node. 16 lanes per edge (uint2 = 4 features). sub = lane>>4 picks
// even/odd edge of each pair; software-pipelined CSR prefetch; masked norms.
__global__ __launch_bounds__(256) void k_agg(
    const float* __restrict__ rootf, const float* __restrict__ rootr,
    const float* __restrict__ lg, const float* __restrict__ lb,
    float* __restrict__ out, int off)
{
    int n = blockIdx.x * 8 + (threadIdx.x >> 5);
    int lane = threadIdx.x & 31;
    int sub = lane >> 4;
    int q = lane & 15;
    int begF = g_offF[n], degF = g_cntr[n];
    int begR = g_offR[n], degR = g_cntf[n];
    const int2* csF = g_csrF + begF + sub;
    const int2* csR = g_csrR + begR + sub;
    float4 af = make_float4(0.f, 0.f, 0.f, 0.f);
    float4 ar = make_float4(0.f, 0.f, 0.f, 0.f);
    int dmax = degF > degR ? degF : degR;
    int iters = (dmax + 7) >> 3;
    if (iters > 0) {
        int2 pF0 = __ldcs(csF + 0), pF1 = __ldcs(csF + 2);
        int2 pF2 = __ldcs(csF + 4), pF3 = __ldcs(csF + 6);
        int2 pR0 = __ldcs(csR + 0), pR1 = __ldcs(csR + 2);
        int2 pR2 = __ldcs(csR + 4), pR3 = __ldcs(csR + 6);
        for (int it = 0; it < iters; it++) {
            int base = it * 8 + sub;
            float nF0 = (base + 0 < degF) ? __int_as_float(pF0.y) : 0.f;
            float nF1 = (base + 2 < degF) ? __int_as_float(pF1.y) : 0.f;
            float nF2 = (base + 4 < degF) ? __int_as_float(pF2.y) : 0.f;
            float nF3 = (base + 6 < degF) ? __int_as_float(pF3.y) : 0.f;
            float nR0 = (base + 0 < degR) ? __int_as_float(pR0.y) : 0.f;
            float nR1 = (base + 2 < degR) ? __int_as_float(pR1.y) : 0.f;
            float nR2 = (base + 4 < degR) ? __int_as_float(pR2.y) : 0.f;
            float nR3 = (base + 6 < degR) ? __int_as_float(pR3.y) : 0.f;
            uint2 gF0 = __ldg(g_yf + (size_t)pF0.x * 16 + q);
            uint2 gF1 = __ldg(g_yf + (size_t)pF1.x * 16 + q);
            uint2 gF2 = __ldg(g_yf + (size_t)pF2.x * 16 + q);
            uint2 gF3 = __ldg(g_yf + (size_t)pF3.x * 16 + q);
            uint2 gR0 = __ldg(g_yr + (size_t)pR0.x * 16 + q);
            uint2 gR1 = __ldg(g_yr + (size_t)pR1.x * 16 + q);
            uint2 gR2 = __ldg(g_yr + (size_t)pR2.x * 16 + q);
            uint2 gR3 = __ldg(g_yr + (size_t)pR3.x * 16 + q);
            int nb = (it + 1) * 8;
            pF0 = __ldcs(csF + nb + 0); pF1 = __ldcs(csF + nb + 2);
            pF2 = __ldcs(csF + nb + 4); pF3 = __ldcs(csF + nb + 6);
            pR0 = __ldcs(csR + nb + 0); pR1 = __ldcs(csR + nb + 2);
            pR2 = __ldcs(csR + nb + 4); pR3 = __ldcs(csR + nb + 6);
            acc4(af, gF0, nF0); acc4(af, gF1, nF1);
            acc4(af, gF2, nF2); acc4(af, gF3, nF3);
            acc4(ar, gR0, nR0); acc4(ar, gR1, nR1);
            acc4(ar, gR2, nR2); acc4(ar, gR3, nR3);
        }
    }
    // combine even/odd edge halves
    af.x += __shfl_xor_sync(0xffffffffu, af.x, 16);
    af.y += __shfl_xor_sync(0xffffffffu, af.y, 16);
    af.z += __shfl_xor_sync(0xffffffffu, af.z, 16);
    af.w += __shfl_xor_sync(0xffffffffu, af.w, 16);
    ar.x += __shfl_xor_sync(0xffffffffu, ar.x, 16);
    ar.y += __shfl_xor_sync(0xffffffffu, ar.y, 16);
    ar.z += __shfl_xor_sync(0xffffffffu, ar.z, 16);
    ar.w += __shfl_xor_sync(0xffffffffu, ar.w, 16);
    int d = q * 4;
    float4 fx = __ldcs((const float4*)(g_xf + (size_t)n * 64 + d));
    float4 rx = __ldcs((const float4*)(g_xr + (size_t)n * 64 + d));
    float4 rf = *(const float4*)(rootf + d);
    float4 rr = *(const float4*)(rootr + d);
    float idf = g_idegf[n], idr = g_idegr[n];
    float4 s;
    s.x = af.x + ar.x + fmaxf(fx.x + rf.x, 0.f) * idf + fmaxf(rx.x + rr.x, 0.f) * idr;
    s.y = af.y + ar.y + fmaxf(fx.y + rf.y, 0.f) * idf + fmaxf(rx.y + rr.y, 0.f) * idr;
    s.z = af.z + ar.z + fmaxf(fx.z + rf.z, 0.f) * idf + fmaxf(rx.z + rr.z, 0.f) * idr;
    s.w = af.w + ar.w + fmaxf(fx.w + rf.w, 0.f) * idf + fmaxf(rx.w + rr.w, 0.f) * idr;
    float tot = s.x + s.y + s.z + s.w;
#pragma unroll
    for (int o = 1; o <= 8; o <<= 1) tot += __shfl_xor_sync(0xffffffffu, tot, o);
    float m = tot * (1.0f / 64.0f);
    float4 dx = make_float4(s.x - m, s.y - m, s.z - m, s.w - m);
    float sq = dx.x * dx.x + dx.y * dx.y + dx.z * dx.z + dx.w * dx.w;
#pragma unroll
    for (int o = 1; o <= 8; o <<= 1) sq += __shfl_xor_sync(0xffffffffu, sq, o);
    float inv = rsqrtf(sq * (1.0f / 64.0f) + 1e-5f);
    float4 gg = *(const float4*)(lg + d);
    float4 bb = *(const float4*)(lb + d);
    float4 o4;
    o4.x = leaky(dx.x * inv * gg.x + bb.x);
    o4.y = leaky(dx.y * inv * gg.y + bb.y);
    o4.z = leaky(dx.z * inv * gg.z + bb.z);
    o4.w = leaky(dx.w * inv * gg.w + bb.w);
    if (lane < 16)
        __stcs((float4*)(out + (size_t)n * 256 + off + d), o4);
}

// ---------------- launch ----------------
extern "C" void kernel_launch(void* const* d_in, const int* in_sizes, int n_in,
                              void* d_out, int out_size) {
    const float* x     = (const float*)d_in[0];
    const float* xnet  = (const float*)d_in[1];
    const int*   ei    = (const int*)  d_in[2];
    const float* e1W   = (const float*)d_in[3];
    const float* e1b   = (const float*)d_in[4];
    const float* e2W   = (const float*)d_in[5];
    const float* e2b   = (const float*)d_in[6];
    const float* n1W   = (const float*)d_in[7];
    const float* n1b   = (const float*)d_in[8];
    const float* n2W   = (const float*)d_in[9];
    const float* n2b   = (const float*)d_in[10];
    const float* convW = (const float*)d_in[11];
    const float* convb = (const float*)d_in[12];
    const float* convr = (const float*)d_in[13];
    const float* reW   = (const float*)d_in[14];
    const float* reb   = (const float*)d_in[15];
    const float* rer   = (const float*)d_in[16];
    const float* lng   = (const float*)d_in[17];
    const float* lnb   = (const float*)d_in[18];
    float* out = (float*)d_out;

    void *pcf, *pcr, *pff, *pfr, *poF, *poR, *pbF, *pbR, *pxf, *pxr, *pyf, *pyr, *ptmp, *ptmpn;
    cudaGetSymbolAddress(&pcf, g_cntf);
    cudaGetSymbolAddress(&pcr, g_cntr);
    cudaGetSymbolAddress(&pff, g_fillF);
    cudaGetSymbolAddress(&pfr, g_fillR);
    cudaGetSymbolAddress(&poF, g_offF);
    cudaGetSymbolAddress(&poR, g_offR);
    cudaGetSymbolAddress(&pbF, g_bsF);
    cudaGetSymbolAddress(&pbR, g_bsR);
    cudaGetSymbolAddress(&pxf, g_xf);
    cudaGetSymbolAddress(&pxr, g_xr);
    cudaGetSymbolAddress(&pyf, g_yf);
    cudaGetSymbolAddress(&pyr, g_yr);
    cudaGetSymbolAddress(&ptmp, g_tmp);
    cudaGetSymbolAddress(&ptmpn, g_tmpn);

    static cudaStream_t s2 = []() {
        cudaStream_t s; cudaStreamCreateWithFlags(&s, cudaStreamNonBlocking); return s;
    }();
    static cudaStream_t s3 = []() {
        cudaStream_t s; cudaStreamCreateWithFlags(&s, cudaStreamNonBlocking); return s;
    }();
    auto mkev = []() { cudaEvent_t e; cudaEventCreateWithFlags(&e, cudaEventDisableTiming); return e; };
    static cudaEvent_t evF = mkev();
    static cudaEvent_t evEnc = mkev();
    static cudaEvent_t evCSR = mkev();
    static cudaEvent_t evL[3] = {mkev(), mkev(), mkev()};
    static cudaEvent_t evR[3] = {mkev(), mkev(), mkev()};

    cudaEventRecord(evF, 0);

    // ---- main: encoders (ops 0-3) ----
    k_encA<16, 128, 32><<<N_INST / 32, 256>>>(x, e1W, e1b, (float*)ptmp, N_INST);
    k_mm<128, true, false><<<(N_INST + 63) / 64, 128>>>(
        (const float*)ptmp, 128, 0, 0, e2W, e2b, out, 256, 0, 0, nullptr, N_INST);
    k_encA<8, 64, 32><<<(N_NETN + 31) / 32, 256>>>(xnet, n1W, n1b, (float*)ptmpn, N_NETN);
    k_mm<64, true, false><<<(N_NETN + 63) / 64, 128>>>(
        (const float*)ptmpn, 64, 0, 0, n2W, n2b, out, 256, 0, N_INST, nullptr, N_NETN);
    cudaEventRecord(evEnc, 0);

    // ---- layer-0 GEMMs submitted early (ncu window ~ops 4-5) ----
    k_mm<64, false, true><<<(NN + 63) / 64, 128>>>(
        out, 256, 0, 0, convW, convb, (float*)pxf, 64, 0, 0, (uint2*)pyf, NN);
    cudaStreamWaitEvent(s3, evEnc, 0);
    k_mm<64, false, true><<<(NN + 63) / 64, 128, 0, s3>>>(
        out, 256, 0, 0, reW, reb, (float*)pxr, 64, 0, 0, (uint2*)pyr, NN);
    cudaEventRecord(evR[0], s3);

    // ---- s2: CSR build (overlaps encoders in execution) ----
    cudaStreamWaitEvent(s2, evF, 0);
    cudaMemsetAsync(pcf, 0, NN * sizeof(int), s2);
    cudaMemsetAsync(pcr, 0, NN * sizeof(int), s2);
    cudaMemsetAsync(pff, 0, NN * sizeof(int), s2);
    cudaMemsetAsync(pfr, 0, NN * sizeof(int), s2);
    k_count<<<(NE + 255) / 256, 256, 0, s2>>>(ei);
    k_deg<<<(NN + 255) / 256, 256, 0, s2>>>();
    k_scan1<<<NSCANB, 256, 0, s2>>>((const int*)pcr, (int*)poF, (int*)pbF);
    k_scan1<<<NSCANB, 256, 0, s2>>>((const int*)pcf, (int*)poR, (int*)pbR);
    k_scan2<<<1, 256, 0, s2>>>((int*)pbF, NSCANB);
    k_scan2<<<1, 256, 0, s2>>>((int*)pbR, NSCANB);
    k_scan3<<<NSCANB, 256, 0, s2>>>((int*)poF, (const int*)pbF);
    k_scan3<<<NSCANB, 256, 0, s2>>>((int*)poR, (const int*)pbR);
    k_place<<<(NE + 255) / 256, 256, 0, s2>>>(ei);
    cudaEventRecord(evCSR, s2);

    // ---- layer 0 agg ----
    cudaStreamWaitEvent(0, evR[0], 0);
    cudaStreamWaitEvent(0, evCSR, 0);
    k_agg<<<NN / 8, 256>>>(convr, rer, lng, lnb, out, 64);
    cudaEventRecord(evL[0], 0);

    // ---- layers 1,2 ----
    for (int l = 1; l < 3; l++) {
        k_mm<64, false, true><<<(NN + 63) / 64, 128>>>(
            out, 256, l * 64, 0, convW + l * 4096, convb + l * 64,
            (float*)pxf, 64, 0, 0, (uint2*)pyf, NN);
        cudaStreamWaitEvent(s3, evL[l - 1], 0);
        k_mm<64, false, true><<<(NN + 63) / 64, 128, 0, s3>>>(
            out, 256, l * 64, 0, reW + l * 4096, reb + l * 64,
            (float*)pxr, 64, 0, 0, (uint2*)pyr, NN);
        cudaEventRecord(evR[l], s3);
        cudaStreamWaitEvent(0, evR[l], 0);
        k_agg<<<NN / 8, 256>>>(convr + l * 64, rer + l * 64,
                               lng + l * 64, lnb + l * 64,
                               out, (l + 1) * 64);
        cudaEventRecord(evL[l], 0);
    }
}

// round 7
// speedup vs baseline: 1.1213x; 1.1213x over previous
#include <cuda_runtime.h>
#include <cuda_fp16.h>

#define N_INST 200000
#define N_NETN 50000
#define NN     250000
#define NE     2000000
#define NSCANB 245   // ceil(250000/1024)

// ---------------- device scratch (no runtime allocation allowed) ----------------
__device__ float   g_xf[(size_t)NN * 64];     // x_f = h @ Wf + bf (fp32, self term)
__device__ float   g_xr[(size_t)NN * 64];     // x_r = h @ Wr + br
__device__ __half2 g_yf[(size_t)NN * 32];     // relu(x_f) fp16 (gather payload)
__device__ __half2 g_yr[(size_t)NN * 32];     // relu(x_r) fp16
__device__ float   g_tmp[(size_t)N_INST * 128]; // encoder hidden (inst)
__device__ float   g_tmpn[(size_t)N_NETN * 64]; // encoder hidden (net)
__device__ float   g_disf[NN], g_disr[NN];    // deg^-1/2
__device__ float   g_idegf[NN], g_idegr[NN];  // deg^-1
__device__ int     g_cntf[NN], g_cntr[NN];    // edge counts (row / col)
__device__ int     g_offF[NN], g_offR[NN];    // CSR bucket starts
__device__ int     g_fillF[NN], g_fillR[NN];
__device__ int     g_bsF[256], g_bsR[256];    // scan block sums
__device__ int2    g_csrF[NE];                // (src, norm) bucketed by col
__device__ int2    g_csrR[NE];                // (src, norm) bucketed by row

// ---------------- helpers ----------------
__device__ __forceinline__ float leaky(float v) { return fmaxf(v, 0.1f * v); }

__device__ __forceinline__ unsigned long long dup64(float a) {
    unsigned long long r;
    asm("mov.b64 %0, {%1, %1};" : "=l"(r) : "f"(a));
    return r;
}
__device__ __forceinline__ float2 up64(unsigned long long v) {
    float2 r;
    asm("mov.b64 {%0, %1}, %2;" : "=f"(r.x), "=f"(r.y) : "l"(v));
    return r;
}
__device__ __forceinline__ void fma2(unsigned long long& d,
                                     unsigned long long a,
                                     unsigned long long b) {
    asm("fma.rn.f32x2 %0, %1, %2, %0;" : "+l"(d) : "l"(a), "l"(b));
}

// ---------------- degree counting ----------------
__global__ __launch_bounds__(256) void k_count(const int* __restrict__ ei) {
    int e = blockIdx.x * 256 + threadIdx.x;
    if (e >= NE) return;
    atomicAdd(&g_cntf[ei[e]], 1);
    atomicAdd(&g_cntr[ei[NE + e]], 1);
}

__global__ __launch_bounds__(256) void k_deg() {
    int n = blockIdx.x * 256 + threadIdx.x;
    if (n >= NN) return;
    float df = (float)g_cntf[n] + 1.0f;
    float dr = (float)g_cntr[n] + 1.0f;
    g_disf[n] = rsqrtf(df);
    g_disr[n] = rsqrtf(dr);
    g_idegf[n] = 1.0f / df;
    g_idegr[n] = 1.0f / dr;
}

// ---------------- exclusive scan ----------------
__global__ __launch_bounds__(256) void k_scan1(const int* __restrict__ cnt,
                                               int* __restrict__ off,
                                               int* __restrict__ bsum) {
    __shared__ int wsum[8];
    int tid = threadIdx.x, lane = tid & 31, w = tid >> 5;
    int base = blockIdx.x * 1024 + tid * 4;
    int v0 = (base + 0 < NN) ? cnt[base + 0] : 0;
    int v1 = (base + 1 < NN) ? cnt[base + 1] : 0;
    int v2 = (base + 2 < NN) ? cnt[base + 2] : 0;
    int v3 = (base + 3 < NN) ? cnt[base + 3] : 0;
    int s = v0 + v1 + v2 + v3;
    int x = s;
#pragma unroll
    for (int o = 1; o < 32; o <<= 1) {
        int y = __shfl_up_sync(0xffffffffu, x, o);
        if (lane >= o) x += y;
    }
    if (lane == 31) wsum[w] = x;
    __syncthreads();
    if (tid == 0) {
        int r = 0;
#pragma unroll
        for (int j = 0; j < 8; j++) { int t = wsum[j]; wsum[j] = r; r += t; }
        bsum[blockIdx.x] = r;
    }
    __syncthreads();
    int ex = wsum[w] + x - s;
    if (base + 0 < NN) off[base + 0] = ex;
    if (base + 1 < NN) off[base + 1] = ex + v0;
    if (base + 2 < NN) off[base + 2] = ex + v0 + v1;
    if (base + 3 < NN) off[base + 3] = ex + v0 + v1 + v2;
}

__global__ __launch_bounds__(256) void k_scan2(int* __restrict__ bsum, int nb) {
    __shared__ int sm[256];
    int tid = threadIdx.x;
    int v = (tid < nb) ? bsum[tid] : 0;
    sm[tid] = v;
    __syncthreads();
#pragma unroll
    for (int o = 1; o < 256; o <<= 1) {
        int t = (tid >= o) ? sm[tid - o] : 0;
        __syncthreads();
        sm[tid] += t;
        __syncthreads();
    }
    if (tid < nb) bsum[tid] = sm[tid] - v;
}

__global__ __launch_bounds__(256) void k_scan3(int* __restrict__ off,
                                               const int* __restrict__ bsum) {
    int add = bsum[blockIdx.x];
    int base = blockIdx.x * 1024 + threadIdx.x * 4;
#pragma unroll
    for (int i = 0; i < 4; i++)
        if (base + i < NN) off[base + i] += add;
}

// ---------------- CSR placement with per-edge norms ----------------
__global__ __launch_bounds__(256) void k_place(const int* __restrict__ ei) {
    int e = blockIdx.x * 256 + threadIdx.x;
    if (e >= NE) return;
    int a = __ldg(ei + e);
    int b = __ldg(ei + NE + e);
    float nf = __ldg(&g_disf[a]) * __ldg(&g_disf[b]);
    float nr = __ldg(&g_disr[b]) * __ldg(&g_disr[a]);
    int pf = g_offF[b] + atomicAdd(&g_fillF[b], 1);
    g_csrF[pf] = make_int2(a, __float_as_int(nf));
    int pr = g_offR[a] + atomicAdd(&g_fillR[a], 1);
    g_csrR[pr] = make_int2(b, __float_as_int(nr));
}

// ---------------- encoder stage 1 ----------------
template<int KIN, int KOUT, int NPB>
__global__ __launch_bounds__(256) void k_encA(
    const float* __restrict__ x, const float* __restrict__ W,
    const float* __restrict__ bias, float* __restrict__ tmp, int nNodes)
{
    __shared__ float xs[NPB * KIN];
    int tid = threadIdx.x;
    int base = blockIdx.x * NPB;
    const int NSUB = 256 / KOUT;
#pragma unroll
    for (int i = 0; i < (NPB * KIN + 255) / 256; i++) {
        int idx = tid + i * 256;
        if (idx < NPB * KIN) {
            size_t gidx = (size_t)base * KIN + idx;
            size_t mx = (size_t)nNodes * KIN - 1;
            xs[idx] = x[gidx <= mx ? gidx : mx];
        }
    }
    int j = tid & (KOUT - 1);
    int nsub = tid / KOUT;
    float wcol[KIN];
#pragma unroll
    for (int k = 0; k < KIN; k++) wcol[k] = W[k * KOUT + j];
    float bj = bias[j];
    __syncthreads();
#pragma unroll
    for (int t = 0; t < NPB / NSUB; t++) {
        int n = nsub + t * NSUB;
        float a = bj;
#pragma unroll
        for (int k4 = 0; k4 < KIN; k4 += 4) {
            float4 xv = *(const float4*)&xs[n * KIN + k4];
            a += xv.x * wcol[k4] + xv.y * wcol[k4 + 1]
               + xv.z * wcol[k4 + 2] + xv.w * wcol[k4 + 3];
        }
        if (base + n < nNodes)
            tmp[(size_t)(base + n) * KOUT + j] = leaky(a);
    }
}

// ---------------- register-tiled GEMM (encoders): dst = act(src @ W + b) ----------------
template<int KTOT, bool LEAKY>
__global__ __launch_bounds__(128) void k_mm(
    const float* __restrict__ src, int srcStride, int srcOff, int srcBase,
    const float* __restrict__ W, const float* __restrict__ bias,
    float* __restrict__ dst, int dstStride, int dstOff, int dstBase,
    int nNodes)
{
    __shared__ float hs[64 * 68];
    __shared__ float ws[64 * 64];
    int tid = threadIdx.x;
    int tb = blockIdx.x * 64;
    int tx = tid & 15, ty = tid >> 4;
    int bn = ty * 8;
    unsigned long long acc[4][4];
#pragma unroll
    for (int a = 0; a < 4; a++)
#pragma unroll
        for (int b = 0; b < 4; b++) acc[a][b] = 0ull;

    int c = tid & 63, r = tid >> 6;
    for (int kc = 0; kc < KTOT; kc += 64) {
        if (kc) __syncthreads();
#pragma unroll
        for (int i = 0; i < 32; i++)
            ws[tid + i * 128] = W[kc * 64 + tid + i * 128];
#pragma unroll
        for (int i = 0; i < 32; i++) {
            int nl = i * 2 + r;
            int g = tb + nl; if (g >= nNodes) g = nNodes - 1;
            hs[c * 68 + nl] = src[(size_t)(srcBase + g) * srcStride + srcOff + kc + c];
        }
        __syncthreads();
#pragma unroll 4
        for (int k = 0; k < 64; k++) {
            float4 wf = *(const float4*)&ws[k * 64 + tx * 4];
            unsigned long long dw0 = dup64(wf.x);
            unsigned long long dw1 = dup64(wf.y);
            unsigned long long dw2 = dup64(wf.z);
            unsigned long long dw3 = dup64(wf.w);
            ulonglong2 hA = *(const ulonglong2*)&hs[k * 68 + bn];
            ulonglong2 hB = *(const ulonglong2*)&hs[k * 68 + bn + 4];
            fma2(acc[0][0], hA.x, dw0); fma2(acc[0][1], hA.x, dw1);
            fma2(acc[0][2], hA.x, dw2); fma2(acc[0][3], hA.x, dw3);
            fma2(acc[1][0], hA.y, dw0); fma2(acc[1][1], hA.y, dw1);
            fma2(acc[1][2], hA.y, dw2); fma2(acc[1][3], hA.y, dw3);
            fma2(acc[2][0], hB.x, dw0); fma2(acc[2][1], hB.x, dw1);
            fma2(acc[2][2], hB.x, dw2); fma2(acc[2][3], hB.x, dw3);
            fma2(acc[3][0], hB.y, dw0); fma2(acc[3][1], hB.y, dw1);
            fma2(acc[3][2], hB.y, dw2); fma2(acc[3][3], hB.y, dw3);
        }
    }
    float4 bv = *(const float4*)&bias[tx * 4];
#pragma unroll
    for (int np = 0; np < 4; np++) {
        int n0 = tb + bn + np * 2;
        float2 v0 = up64(acc[np][0]);
        float2 v1 = up64(acc[np][1]);
        float2 v2 = up64(acc[np][2]);
        float2 v3 = up64(acc[np][3]);
        float4 o0 = make_float4(v0.x + bv.x, v1.x + bv.y, v2.x + bv.z, v3.x + bv.w);
        float4 o1 = make_float4(v0.y + bv.x, v1.y + bv.y, v2.y + bv.z, v3.y + bv.w);
        if (LEAKY) {
            o0 = make_float4(leaky(o0.x), leaky(o0.y), leaky(o0.z), leaky(o0.w));
            o1 = make_float4(leaky(o1.x), leaky(o1.y), leaky(o1.z), leaky(o1.w));
        }
        if (n0 < nNodes)
            *(float4*)&dst[(size_t)(dstBase + n0) * dstStride + dstOff + tx * 4] = o0;
        if (n0 + 1 < nNodes)
            *(float4*)&dst[(size_t)(dstBase + n0 + 1) * dstStride + dstOff + tx * 4] = o1;
    }
}

// ---------------- fused dual conv GEMM: xf = h@Wf+bf, xr = h@Wr+br (+fp16 relu) ----
// h tile loaded ONCE to smem, two weight phases reuse it.
__global__ __launch_bounds__(128) void k_mm2(
    const float* __restrict__ src, int srcOff,
    const float* __restrict__ Wf, const float* __restrict__ bf,
    const float* __restrict__ Wr, const float* __restrict__ br)
{
    __shared__ float hs[64 * 68];
    __shared__ float ws[64 * 64];
    int tid = threadIdx.x;
    int tb = blockIdx.x * 64;
    int tx = tid & 15, ty = tid >> 4;
    int bn = ty * 8;
    int c = tid & 63, r = tid >> 6;
    // load h tile once (stride 256 = d_out rows)
#pragma unroll
    for (int i = 0; i < 32; i++) {
        int nl = i * 2 + r;
        int g = tb + nl; if (g >= NN) g = NN - 1;
        hs[c * 68 + nl] = src[(size_t)g * 256 + srcOff + c];
    }

#pragma unroll
    for (int ph = 0; ph < 2; ph++) {
        const float* W    = ph ? Wr : Wf;
        const float* bias = ph ? br : bf;
        float*       dst  = ph ? g_xr : g_xf;
        __half2*     yout = ph ? g_yr : g_yf;
        __syncthreads();
#pragma unroll
        for (int i = 0; i < 32; i++)
            ws[tid + i * 128] = W[tid + i * 128];
        __syncthreads();
        unsigned long long acc[4][4];
#pragma unroll
        for (int a = 0; a < 4; a++)
#pragma unroll
            for (int b = 0; b < 4; b++) acc[a][b] = 0ull;
#pragma unroll 4
        for (int k = 0; k < 64; k++) {
            float4 wf = *(const float4*)&ws[k * 64 + tx * 4];
            unsigned long long dw0 = dup64(wf.x);
            unsigned long long dw1 = dup64(wf.y);
            unsigned long long dw2 = dup64(wf.z);
            unsigned long long dw3 = dup64(wf.w);
            ulonglong2 hA = *(const ulonglong2*)&hs[k * 68 + bn];
            ulonglong2 hB = *(const ulonglong2*)&hs[k * 68 + bn + 4];
            fma2(acc[0][0], hA.x, dw0); fma2(acc[0][1], hA.x, dw1);
            fma2(acc[0][2], hA.x, dw2); fma2(acc[0][3], hA.x, dw3);
            fma2(acc[1][0], hA.y, dw0); fma2(acc[1][1], hA.y, dw1);
            fma2(acc[1][2], hA.y, dw2); fma2(acc[1][3], hA.y, dw3);
            fma2(acc[2][0], hB.x, dw0); fma2(acc[2][1], hB.x, dw1);
            fma2(acc[2][2], hB.x, dw2); fma2(acc[2][3], hB.x, dw3);
            fma2(acc[3][0], hB.y, dw0); fma2(acc[3][1], hB.y, dw1);
            fma2(acc[3][2], hB.y, dw2); fma2(acc[3][3], hB.y, dw3);
        }
        float4 bv = *(const float4*)&bias[tx * 4];
#pragma unroll
        for (int np = 0; np < 4; np++) {
            int n0 = tb + bn + np * 2;
            float2 v0 = up64(acc[np][0]);
            float2 v1 = up64(acc[np][1]);
            float2 v2 = up64(acc[np][2]);
            float2 v3 = up64(acc[np][3]);
            float4 o0 = make_float4(v0.x + bv.x, v1.x + bv.y, v2.x + bv.z, v3.x + bv.w);
            float4 o1 = make_float4(v0.y + bv.x, v1.y + bv.y, v2.y + bv.z, v3.y + bv.w);
            if (n0 < NN) {
                *(float4*)&dst[(size_t)n0 * 64 + tx * 4] = o0;
                __half2 h0 = __float22half2_rn(make_float2(fmaxf(o0.x, 0.f), fmaxf(o0.y, 0.f)));
                __half2 h1 = __float22half2_rn(make_float2(fmaxf(o0.z, 0.f), fmaxf(o0.w, 0.f)));
                *(uint2*)&yout[(size_t)n0 * 32 + tx * 2] =
                    make_uint2(*(unsigned*)&h0, *(unsigned*)&h1);
            }
            if (n0 + 1 < NN) {
                *(float4*)&dst[(size_t)(n0 + 1) * 64 + tx * 4] = o1;
                __half2 h0 = __float22half2_rn(make_float2(fmaxf(o1.x, 0.f), fmaxf(o1.y, 0.f)));
                __half2 h1 = __float22half2_rn(make_float2(fmaxf(o1.z, 0.f), fmaxf(o1.w, 0.f)));
                *(uint2*)&yout[(size_t)(n0 + 1) * 32 + tx * 2] =
                    make_uint2(*(unsigned*)&h0, *(unsigned*)&h1);
            }
        }
    }
}

// ---------------- fused aggregation (fwd + rev) + self terms + LayerNorm + leaky ----------------
__global__ __launch_bounds__(256) void k_agg(
    const float* __restrict__ rootf, const float* __restrict__ rootr,
    const float* __restrict__ lg, const float* __restrict__ lb,
    float* __restrict__ out, int off)
{
    int n = blockIdx.x * 8 + (threadIdx.x >> 5);
    int lane = threadIdx.x & 31;
    int d = lane * 2;
    int begF = g_offF[n], degF = g_cntr[n];   // fwd buckets keyed by col
    int begR = g_offR[n], degR = g_cntf[n];   // rev buckets keyed by row
    float2 af = make_float2(0.f, 0.f);
    float2 ar = make_float2(0.f, 0.f);
    {
        const int2* cs = g_csrF + begF;
        const __half2* Y = g_yf;
        int i = 0;
        for (; i + 4 <= degF; i += 4) {
            int2 e0 = __ldg(cs + i), e1 = __ldg(cs + i + 1);
            int2 e2 = __ldg(cs + i + 2), e3 = __ldg(cs + i + 3);
            float2 v0 = __half22float2(__ldg(Y + (size_t)e0.x * 32 + lane));
            float2 v1 = __half22float2(__ldg(Y + (size_t)e1.x * 32 + lane));
            float2 v2 = __half22float2(__ldg(Y + (size_t)e2.x * 32 + lane));
            float2 v3 = __half22float2(__ldg(Y + (size_t)e3.x * 32 + lane));
            float n0 = __int_as_float(e0.y), n1 = __int_as_float(e1.y);
            float n2 = __int_as_float(e2.y), n3 = __int_as_float(e3.y);
            af.x += v0.x * n0 + v1.x * n1 + v2.x * n2 + v3.x * n3;
            af.y += v0.y * n0 + v1.y * n1 + v2.y * n2 + v3.y * n3;
        }
        for (; i < degF; i++) {
            int2 e0 = __ldg(cs + i);
            float2 v0 = __half22float2(__ldg(Y + (size_t)e0.x * 32 + lane));
            float n0 = __int_as_float(e0.y);
            af.x += v0.x * n0;
            af.y += v0.y * n0;
        }
    }
    {
        const int2* cs = g_csrR + begR;
        const __half2* Y = g_yr;
        int i = 0;
        for (; i + 4 <= degR; i += 4) {
            int2 e0 = __ldg(cs + i), e1 = __ldg(cs + i + 1);
            int2 e2 = __ldg(cs + i + 2), e3 = __ldg(cs + i + 3);
            float2 v0 = __half22float2(__ldg(Y + (size_t)e0.x * 32 + lane));
            float2 v1 = __half22float2(__ldg(Y + (size_t)e1.x * 32 + lane));
            float2 v2 = __half22float2(__ldg(Y + (size_t)e2.x * 32 + lane));
            float2 v3 = __half22float2(__ldg(Y + (size_t)e3.x * 32 + lane));
            float n0 = __int_as_float(e0.y), n1 = __int_as_float(e1.y);
            float n2 = __int_as_float(e2.y), n3 = __int_as_float(e3.y);
            ar.x += v0.x * n0 + v1.x * n1 + v2.x * n2 + v3.x * n3;
            ar.y += v0.y * n0 + v1.y * n1 + v2.y * n2 + v3.y * n3;
        }
        for (; i < degR; i++) {
            int2 e0 = __ldg(cs + i);
            float2 v0 = __half22float2(__ldg(Y + (size_t)e0.x * 32 + lane));
            float n0 = __int_as_float(e0.y);
            ar.x += v0.x * n0;
            ar.y += v0.y * n0;
        }
    }
    size_t o64 = (size_t)n * 64 + d;
    float2 fx = *(const float2*)&g_xf[o64];
    float2 rx = *(const float2*)&g_xr[o64];
    float idf = g_idegf[n], idr = g_idegr[n];
    float s0 = af.x + ar.x + fmaxf(fx.x + rootf[d], 0.f) * idf
                           + fmaxf(rx.x + rootr[d], 0.f) * idr;
    float s1 = af.y + ar.y + fmaxf(fx.y + rootf[d + 1], 0.f) * idf
                           + fmaxf(rx.y + rootr[d + 1], 0.f) * idr;
    float sum = s0 + s1;
#pragma unroll
    for (int o = 16; o > 0; o >>= 1) sum += __shfl_xor_sync(0xffffffffu, sum, o);
    float m = sum * (1.0f / 64.0f);
    float d0 = s0 - m, d1 = s1 - m;
    float sq = d0 * d0 + d1 * d1;
#pragma unroll
    for (int o = 16; o > 0; o >>= 1) sq += __shfl_xor_sync(0xffffffffu, sq, o);
    float inv = rsqrtf(sq * (1.0f / 64.0f) + 1e-5f);
    float o0 = leaky(d0 * inv * lg[d] + lb[d]);
    float o1 = leaky(d1 * inv * lg[d + 1] + lb[d + 1]);
    *(float2*)&out[(size_t)n * 256 + off + d] = make_float2(o0, o1);
}

// ---------------- launch ----------------
extern "C" void kernel_launch(void* const* d_in, const int* in_sizes, int n_in,
                              void* d_out, int out_size) {
    const float* x     = (const float*)d_in[0];
    const float* xnet  = (const float*)d_in[1];
    const int*   ei    = (const int*)  d_in[2];
    const float* e1W   = (const float*)d_in[3];
    const float* e1b   = (const float*)d_in[4];
    const float* e2W   = (const float*)d_in[5];
    const float* e2b   = (const float*)d_in[6];
    const float* n1W   = (const float*)d_in[7];
    const float* n1b   = (const float*)d_in[8];
    const float* n2W   = (const float*)d_in[9];
    const float* n2b   = (const float*)d_in[10];
    const float* convW = (const float*)d_in[11];
    const float* convb = (const float*)d_in[12];
    const float* convr = (const float*)d_in[13];
    const float* reW   = (const float*)d_in[14];
    const float* reb   = (const float*)d_in[15];
    const float* rer   = (const float*)d_in[16];
    const float* lng   = (const float*)d_in[17];
    const float* lnb   = (const float*)d_in[18];
    float* out = (float*)d_out;

    void *pcf, *pcr, *pff, *pfr, *poF, *poR, *pbF, *pbR, *ptmp, *ptmpn;
    cudaGetSymbolAddress(&pcf, g_cntf);
    cudaGetSymbolAddress(&pcr, g_cntr);
    cudaGetSymbolAddress(&pff, g_fillF);
    cudaGetSymbolAddress(&pfr, g_fillR);
    cudaGetSymbolAddress(&poF, g_offF);
    cudaGetSymbolAddress(&poR, g_offR);
    cudaGetSymbolAddress(&pbF, g_bsF);
    cudaGetSymbolAddress(&pbR, g_bsR);
    cudaGetSymbolAddress(&ptmp, g_tmp);
    cudaGetSymbolAddress(&ptmpn, g_tmpn);

    static cudaStream_t s2 = []() {
        cudaStream_t s; cudaStreamCreateWithFlags(&s, cudaStreamNonBlocking); return s;
    }();
    auto mkev = []() { cudaEvent_t e; cudaEventCreateWithFlags(&e, cudaEventDisableTiming); return e; };
    static cudaEvent_t evF = mkev();
    static cudaEvent_t evCSR = mkev();

    cudaEventRecord(evF, 0);

    // ---- s2: CSR build (overlaps encoders) ----
    cudaStreamWaitEvent(s2, evF, 0);
    cudaMemsetAsync(pcf, 0, NN * sizeof(int), s2);
    cudaMemsetAsync(pcr, 0, NN * sizeof(int), s2);
    cudaMemsetAsync(pff, 0, NN * sizeof(int), s2);
    cudaMemsetAsync(pfr, 0, NN * sizeof(int), s2);
    k_count<<<(NE + 255) / 256, 256, 0, s2>>>(ei);
    k_deg<<<(NN + 255) / 256, 256, 0, s2>>>();
    k_scan1<<<NSCANB, 256, 0, s2>>>((const int*)pcr, (int*)poF, (int*)pbF);
    k_scan1<<<NSCANB, 256, 0, s2>>>((const int*)pcf, (int*)poR, (int*)pbR);
    k_scan2<<<1, 256, 0, s2>>>((int*)pbF, NSCANB);
    k_scan2<<<1, 256, 0, s2>>>((int*)pbR, NSCANB);
    k_scan3<<<NSCANB, 256, 0, s2>>>((int*)poF, (const int*)pbF);
    k_scan3<<<NSCANB, 256, 0, s2>>>((int*)poR, (const int*)pbR);
    k_place<<<(NE + 255) / 256, 256, 0, s2>>>(ei);
    cudaEventRecord(evCSR, s2);

    // ---- main: encoders ----
    k_encA<16, 128, 32><<<N_INST / 32, 256>>>(x, e1W, e1b, (float*)ptmp, N_INST);
    k_mm<128, true><<<(N_INST + 63) / 64, 128>>>(
        (const float*)ptmp, 128, 0, 0, e2W, e2b, out, 256, 0, 0, N_INST);
    k_encA<8, 64, 32><<<(N_NETN + 31) / 32, 256>>>(xnet, n1W, n1b, (float*)ptmpn, N_NETN);
    k_mm<64, true><<<(N_NETN + 63) / 64, 128>>>(
        (const float*)ptmpn, 64, 0, 0, n2W, n2b, out, 256, 0, N_INST, N_NETN);

    // ---- layers: fused dual GEMM -> fused agg ----
    cudaStreamWaitEvent(0, evCSR, 0);
    for (int l = 0; l < 3; l++) {
        k_mm2<<<(NN + 63) / 64, 128>>>(
            out, l * 64,
            convW + l * 4096, convb + l * 64,
            reW + l * 4096,   reb + l * 64);
        k_agg<<<NN / 8, 256>>>(convr + l * 64, rer + l * 64,
                               lng + l * 64, lnb + l * 64,
                               out, (l + 1) * 64);
    }
}